// round 15
// baseline (speedup 1.0000x reference)
#include <cuda_runtime.h>
#include <cstdint>

// ---------------------------------------------------------------------------
// Coo2Cel: periodic minimum-image pair displacements within cutoff.
// Inputs: pos_xyz [B,N,3] f32, cel_mat [B,3,3] f32, pbc [B,3] i32, ent [B,N] i32
// Output (single f32 buffer): vec [B,N,N,3] ++ sod [B,N,N] ++ mask [B,N,N]
//
// Single fused kernel: SMEM-staged stores drained via cp.async.bulk
// (evict_first), warp-private double-buffered pipelines, zero block barriers.
// R15: compute packed as f32x2 (PTX add/mul/fma.rn.f32x2); minimum-image
// round via magic constant (exact round-half-even for |d|<2^22).
// ---------------------------------------------------------------------------

#define RC2 36.0f   // rc = 6.0
#define I_TILE 4
#define JBLK 512          // j's per block (128 threads x 4)
#define WJ 128            // j's per warp
#define WARP_FLOATS (WJ * 5)   // 640: vec 384 | sod 128 | mask 128
#define W_SOD (WJ * 3)         // 384
#define W_MSK (WJ * 4)         // 512
#define RMAGIC 12582912.0f     // 1.5 * 2^23

__device__ __forceinline__ uint32_t smem_u32(const void* p) {
    uint32_t a;
    asm("{ .reg .u64 t; cvta.to.shared.u64 t, %1; cvt.u32.u64 %0, t; }"
        : "=r"(a) : "l"(p));
    return a;
}

__device__ __forceinline__ void bulk_store_ef(const float* gdst, uint32_t ssrc,
                                              int nbytes, uint64_t policy) {
    asm volatile(
        "cp.async.bulk.global.shared::cta.bulk_group.L2::cache_hint "
        "[%0], [%1], %2, %3;"
        :: "l"(gdst), "r"(ssrc), "r"(nbytes), "l"(policy) : "memory");
}

// ---- packed f32x2 helpers ----
__device__ __forceinline__ uint64_t pk2(float lo, float hi) {
    uint64_t r; asm("mov.b64 %0, {%1, %2};" : "=l"(r) : "f"(lo), "f"(hi)); return r;
}
__device__ __forceinline__ void upk2(uint64_t v, float& lo, float& hi) {
    asm("mov.b64 {%0, %1}, %2;" : "=f"(lo), "=f"(hi) : "l"(v));
}
__device__ __forceinline__ uint64_t add2(uint64_t a, uint64_t b) {
    uint64_t r; asm("add.rn.f32x2 %0, %1, %2;" : "=l"(r) : "l"(a), "l"(b)); return r;
}
__device__ __forceinline__ uint64_t mul2(uint64_t a, uint64_t b) {
    uint64_t r; asm("mul.rn.f32x2 %0, %1, %2;" : "=l"(r) : "l"(a), "l"(b)); return r;
}
__device__ __forceinline__ uint64_t fma2(uint64_t a, uint64_t b, uint64_t c) {
    uint64_t r; asm("fma.rn.f32x2 %0, %1, %2, %3;" : "=l"(r) : "l"(a), "l"(b), "l"(c)); return r;
}

__global__ void __launch_bounds__(128)
pair_kernel(const float* __restrict__ pos,
            const float* __restrict__ cel,
            const int*   __restrict__ pbc,
            const int*   __restrict__ ent,
            float* __restrict__ out,
            int N, int B)
{
    __shared__ __align__(16) float sbuf[2][4][WARP_FLOATS];

    const int b    = blockIdx.z;
    const int i0   = blockIdx.y * I_TILE;
    const int jb   = blockIdx.x * JBLK;
    const int warp = threadIdx.x >> 5;
    const int lane = threadIdx.x & 31;
    const int jwb  = jb + warp * WJ;
    const int j0   = jwb + lane * 4;

    // --- cell matrix + inverse (prologue) -----------------------------------
    const float* c = cel + b * 9;
    const float c00 = c[0], c01 = c[1], c02 = c[2];
    const float c10 = c[3], c11 = c[4], c12 = c[5];
    const float c20 = c[6], c21 = c[7], c22 = c[8];

    const float det = c00 * (c11 * c22 - c12 * c21)
                    - c01 * (c10 * c22 - c12 * c20)
                    + c02 * (c10 * c21 - c11 * c20);
    const float r = 1.0f / det;
    const float i00 = (c11 * c22 - c12 * c21) * r;
    const float i01 = (c02 * c21 - c01 * c22) * r;
    const float i02 = (c01 * c12 - c02 * c11) * r;
    const float i10 = (c12 * c20 - c10 * c22) * r;
    const float i11 = (c00 * c22 - c02 * c20) * r;
    const float i12 = (c02 * c10 - c00 * c12) * r;
    const float i20 = (c10 * c21 - c11 * c20) * r;
    const float i21 = (c01 * c20 - c00 * c21) * r;
    const float i22 = (c00 * c11 - c01 * c10) * r;

    const float pb0 = pbc[b * 3 + 0] ? 1.0f : 0.0f;
    const float pb1 = pbc[b * 3 + 1] ? 1.0f : 0.0f;
    const float pb2 = pbc[b * 3 + 2] ? 1.0f : 0.0f;

    uint64_t policy;
    asm("createpolicy.fractional.L2::evict_first.b64 %0, 1.0;" : "=l"(policy));

    // hoisted packed constants
    const uint64_t MAG2  = pk2( RMAGIC,  RMAGIC);
    const uint64_t NMAG2 = pk2(-RMAGIC, -RMAGIC);
    const uint64_t NPB0  = pk2(-pb0, -pb0);
    const uint64_t NPB1  = pk2(-pb1, -pb1);
    const uint64_t NPB2  = pk2(-pb2, -pb2);
    const uint64_t C00 = pk2(c00, c00), C01 = pk2(c01, c01), C02 = pk2(c02, c02);
    const uint64_t C10 = pk2(c10, c10), C11 = pk2(c11, c11), C12 = pk2(c12, c12);
    const uint64_t C20 = pk2(c20, c20), C21 = pk2(c21, c21), C22 = pk2(c22, c22);

    const int base = b * N;

    // --- j-side fracs, packed as 2 pairs (k=0,1) and (k=2,3) ---------------
    const float4* pj4 = reinterpret_cast<const float4*>(pos + ((size_t)base + j0) * 3);
    const float4 pa = pj4[0];
    const float4 pb4 = pj4[1];
    const float4 pc = pj4[2];
    const float pj[12] = { pa.x, pa.y, pa.z, pa.w,
                           pb4.x, pb4.y, pb4.z, pb4.w,
                           pc.x, pc.y, pc.z, pc.w };

    float fjx[4], fjy[4], fjz[4];
    #pragma unroll
    for (int k = 0; k < 4; ++k) {
        const float p0 = pj[k * 3 + 0];
        const float p1 = pj[k * 3 + 1];
        const float p2 = pj[k * 3 + 2];
        fjx[k] = p0 * i00 + p1 * i10 + p2 * i20;
        fjy[k] = p0 * i01 + p1 * i11 + p2 * i21;
        fjz[k] = p0 * i02 + p1 * i12 + p2 * i22;
    }
    const uint64_t FJX[2] = { pk2(fjx[0], fjx[1]), pk2(fjx[2], fjx[3]) };
    const uint64_t FJY[2] = { pk2(fjy[0], fjy[1]), pk2(fjy[2], fjy[3]) };
    const uint64_t FJZ[2] = { pk2(fjz[0], fjz[1]), pk2(fjz[2], fjz[3]) };

    const int4 ej4 = *reinterpret_cast<const int4*>(ent + base + j0);
    const bool ej[4] = { ej4.x != 0, ej4.y != 0, ej4.z != 0, ej4.w != 0 };

    const size_t NN       = (size_t)N * N;
    const size_t sod_off  = (size_t)B * NN * 3;
    const size_t mask_off = (size_t)B * NN * 4;

    #pragma unroll 1
    for (int t = 0; t < I_TILE; ++t) {
        const int i = i0 + t;
        float* buf = sbuf[t & 1][warp];

        if (t >= 2) {
            if (lane == 0)
                asm volatile("cp.async.bulk.wait_group.read 1;" ::: "memory");
            __syncwarp();
        }

        // i-side frac (broadcast loads + one mat-vec)
        const float q0 = pos[((size_t)base + i) * 3 + 0];
        const float q1 = pos[((size_t)base + i) * 3 + 1];
        const float q2 = pos[((size_t)base + i) * 3 + 2];
        const float fi0 = q0 * i00 + q1 * i10 + q2 * i20;
        const float fi1 = q0 * i01 + q1 * i11 + q2 * i21;
        const float fi2 = q0 * i02 + q1 * i12 + q2 * i22;
        const bool  ent_i = ent[base + i] != 0;

        const uint64_t NFI0 = pk2(-fi0, -fi0);
        const uint64_t NFI1 = pk2(-fi1, -fi1);
        const uint64_t NFI2 = pk2(-fi2, -fi2);

        float vx[4], vy[4], vz[4], sd[4], mk[4];

        #pragma unroll
        for (int p = 0; p < 2; ++p) {
            // d = fj - fi  (packed)
            uint64_t d0 = add2(FJX[p], NFI0);
            uint64_t d1 = add2(FJY[p], NFI1);
            uint64_t d2 = add2(FJZ[p], NFI2);

            // rint(d) via magic add/sub (exact round-half-even, |d|<1)
            uint64_t r0 = add2(add2(d0, MAG2), NMAG2);
            uint64_t r1 = add2(add2(d1, MAG2), NMAG2);
            uint64_t r2 = add2(add2(d2, MAG2), NMAG2);

            // d -= rint(d) * pb   (fma with -pb)
            d0 = fma2(r0, NPB0, d0);
            d1 = fma2(r1, NPB1, d1);
            d2 = fma2(r2, NPB2, d2);

            // v = d @ C  (packed)
            uint64_t v0 = fma2(d2, C20, fma2(d1, C10, mul2(d0, C00)));
            uint64_t v1 = fma2(d2, C21, fma2(d1, C11, mul2(d0, C01)));
            uint64_t v2 = fma2(d2, C22, fma2(d1, C12, mul2(d0, C02)));

            // s = |v|^2  (packed)
            uint64_t s2 = fma2(v2, v2, fma2(v1, v1, mul2(v0, v0)));

            float s_lo, s_hi;
            upk2(s2, s_lo, s_hi);

            const int k0 = p * 2;
            const bool ok0 = ent_i && ej[k0]     && (i != j0 + k0)     && (s_lo < RC2);
            const bool ok1 = ent_i && ej[k0 + 1] && (i != j0 + k0 + 1) && (s_hi < RC2);
            const float m0 = ok0 ? 1.0f : 0.0f;
            const float m1 = ok1 ? 1.0f : 0.0f;
            const uint64_t M2 = pk2(m0, m1);

            upk2(mul2(v0, M2), vx[k0], vx[k0 + 1]);
            upk2(mul2(v1, M2), vy[k0], vy[k0 + 1]);
            upk2(mul2(v2, M2), vz[k0], vz[k0 + 1]);
            upk2(mul2(s2, M2), sd[k0], sd[k0 + 1]);
            mk[k0] = m0; mk[k0 + 1] = m1;
        }

        // stage into warp-private SMEM slice (STS.128)
        float4* vdst = reinterpret_cast<float4*>(buf + lane * 12);
        vdst[0] = make_float4(vx[0], vy[0], vz[0], vx[1]);
        vdst[1] = make_float4(vy[1], vz[1], vx[2], vy[2]);
        vdst[2] = make_float4(vz[2], vx[3], vy[3], vz[3]);
        *reinterpret_cast<float4*>(buf + W_SOD + lane * 4) =
            make_float4(sd[0], sd[1], sd[2], sd[3]);
        *reinterpret_cast<float4*>(buf + W_MSK + lane * 4) =
            make_float4(mk[0], mk[1], mk[2], mk[3]);

        __syncwarp();

        if (lane == 0) {
            asm volatile("fence.proxy.async.shared::cta;" ::: "memory");
            const size_t pair = ((size_t)base + i) * N + jwb;
            bulk_store_ef(out + pair * 3,        smem_u32(buf),         WJ * 3 * 4, policy);
            bulk_store_ef(out + sod_off + pair,  smem_u32(buf + W_SOD), WJ * 4,     policy);
            bulk_store_ef(out + mask_off + pair, smem_u32(buf + W_MSK), WJ * 4,     policy);
            asm volatile("cp.async.bulk.commit_group;" ::: "memory");
        }
        __syncwarp();
    }

    // SMEM must stay alive until this warp's TMA reads complete
    if (lane == 0)
        asm volatile("cp.async.bulk.wait_group.read 0;" ::: "memory");
    __syncwarp();
}

extern "C" void kernel_launch(void* const* d_in, const int* in_sizes, int n_in,
                              void* d_out, int out_size)
{
    const float* pos = (const float*)d_in[0];
    const float* cel = (const float*)d_in[1];
    const int*   pbc = (const int*)  d_in[2];
    const int*   ent = (const int*)  d_in[3];
    float* out = (float*)d_out;

    const int B = in_sizes[1] / 9;          // cel_mat has B*9 elements
    const int N = in_sizes[3] / B;          // ent has B*N elements

    dim3 threads(128, 1, 1);
    dim3 blocks(N / JBLK, N / I_TILE, B);
    pair_kernel<<<blocks, threads>>>(pos, cel, pbc, ent, out, N, B);
}

// round 16
// speedup vs baseline: 1.0003x; 1.0003x over previous
#include <cuda_runtime.h>
#include <cstdint>

// ---------------------------------------------------------------------------
// Coo2Cel: periodic minimum-image pair displacements within cutoff.
// Inputs: pos_xyz [B,N,3] f32, cel_mat [B,3,3] f32, pbc [B,3] i32, ent [B,N] i32
// Output (single f32 buffer): vec [B,N,N,3] ++ sod [B,N,N] ++ mask [B,N,N]
//
// FINAL (== R14 champion, 92.7us / DRAM 84%):
//  - single fused kernel; frac coords recomputed per block prologue
//  - compute -> STS.128 into warp-private double buffers
//  - drained via cp.async.bulk (bulk_group) with L2::evict_first hint,
//    bypassing the STG.128 issue-cost wall (12 cyc/inst on sm_103a)
//  - zero block-wide barriers: per-warp pipelines with __syncwarp only
// Bracketing experiments that all regressed: NBUF=3, I_TILE=8/16,
// reg-capped occupancy, f32x2 packed math. This sits at the HBM3e
// pure-write roofline (~6.6-7.3 TB/s effective).
// ---------------------------------------------------------------------------

#define RC2 36.0f   // rc = 6.0
#define I_TILE 4
#define JBLK 512          // j's per block (128 threads x 4)
#define WJ 128            // j's per warp
#define WARP_FLOATS (WJ * 5)   // 640: vec 384 | sod 128 | mask 128
#define W_SOD (WJ * 3)         // 384
#define W_MSK (WJ * 4)         // 512

__device__ __forceinline__ uint32_t smem_u32(const void* p) {
    uint32_t a;
    asm("{ .reg .u64 t; cvta.to.shared.u64 t, %1; cvt.u32.u64 %0, t; }"
        : "=r"(a) : "l"(p));
    return a;
}

__device__ __forceinline__ void bulk_store_ef(const float* gdst, uint32_t ssrc,
                                              int nbytes, uint64_t policy) {
    asm volatile(
        "cp.async.bulk.global.shared::cta.bulk_group.L2::cache_hint "
        "[%0], [%1], %2, %3;"
        :: "l"(gdst), "r"(ssrc), "r"(nbytes), "l"(policy) : "memory");
}

__global__ void __launch_bounds__(128)
pair_kernel(const float* __restrict__ pos,
            const float* __restrict__ cel,
            const int*   __restrict__ pbc,
            const int*   __restrict__ ent,
            float* __restrict__ out,
            int N, int B)
{
    // [buffer][warp][floats] — each warp's slice is contiguous & 16B aligned
    __shared__ __align__(16) float sbuf[2][4][WARP_FLOATS];

    const int b    = blockIdx.z;
    const int i0   = blockIdx.y * I_TILE;
    const int jb   = blockIdx.x * JBLK;
    const int warp = threadIdx.x >> 5;
    const int lane = threadIdx.x & 31;
    const int jwb  = jb + warp * WJ;      // warp's j base
    const int j0   = jwb + lane * 4;

    // --- cell matrix + inverse (prologue; registers die after use) ---------
    const float* c = cel + b * 9;
    const float c00 = c[0], c01 = c[1], c02 = c[2];
    const float c10 = c[3], c11 = c[4], c12 = c[5];
    const float c20 = c[6], c21 = c[7], c22 = c[8];

    const float det = c00 * (c11 * c22 - c12 * c21)
                    - c01 * (c10 * c22 - c12 * c20)
                    + c02 * (c10 * c21 - c11 * c20);
    const float r = 1.0f / det;
    const float i00 = (c11 * c22 - c12 * c21) * r;
    const float i01 = (c02 * c21 - c01 * c22) * r;
    const float i02 = (c01 * c12 - c02 * c11) * r;
    const float i10 = (c12 * c20 - c10 * c22) * r;
    const float i11 = (c00 * c22 - c02 * c20) * r;
    const float i12 = (c02 * c10 - c00 * c12) * r;
    const float i20 = (c10 * c21 - c11 * c20) * r;
    const float i21 = (c01 * c20 - c00 * c21) * r;
    const float i22 = (c00 * c11 - c01 * c10) * r;

    const float pb0 = pbc[b * 3 + 0] ? 1.0f : 0.0f;
    const float pb1 = pbc[b * 3 + 1] ? 1.0f : 0.0f;
    const float pb2 = pbc[b * 3 + 2] ? 1.0f : 0.0f;

    // evict_first policy for write-once output
    uint64_t policy;
    asm("createpolicy.fractional.L2::evict_first.b64 %0, 1.0;" : "=l"(policy));

    const int base = b * N;

    // --- j-side fracs: computed ONCE from pos, reused for all I_TILE i's ---
    const float4* pj4 = reinterpret_cast<const float4*>(pos + ((size_t)base + j0) * 3);
    const float4 pa = pj4[0];
    const float4 pb4 = pj4[1];
    const float4 pc = pj4[2];
    const float pj[12] = { pa.x, pa.y, pa.z, pa.w,
                           pb4.x, pb4.y, pb4.z, pb4.w,
                           pc.x, pc.y, pc.z, pc.w };

    float fjx[4], fjy[4], fjz[4];
    #pragma unroll
    for (int k = 0; k < 4; ++k) {
        const float p0 = pj[k * 3 + 0];
        const float p1 = pj[k * 3 + 1];
        const float p2 = pj[k * 3 + 2];
        fjx[k] = p0 * i00 + p1 * i10 + p2 * i20;
        fjy[k] = p0 * i01 + p1 * i11 + p2 * i21;
        fjz[k] = p0 * i02 + p1 * i12 + p2 * i22;
    }

    const int4 ej4 = *reinterpret_cast<const int4*>(ent + base + j0);
    const bool ej[4] = { ej4.x != 0, ej4.y != 0, ej4.z != 0, ej4.w != 0 };

    const size_t NN       = (size_t)N * N;
    const size_t sod_off  = (size_t)B * NN * 3;
    const size_t mask_off = (size_t)B * NN * 4;

    #pragma unroll 1
    for (int t = 0; t < I_TILE; ++t) {
        const int i = i0 + t;
        float* buf = sbuf[t & 1][warp];

        // per-warp backpressure: this buffer's group committed at t-2
        if (t >= 2) {
            if (lane == 0)
                asm volatile("cp.async.bulk.wait_group.read 1;" ::: "memory");
            __syncwarp();
        }

        // i-side frac: broadcast loads + one mat-vec (cheap)
        const float q0 = pos[((size_t)base + i) * 3 + 0];
        const float q1 = pos[((size_t)base + i) * 3 + 1];
        const float q2 = pos[((size_t)base + i) * 3 + 2];
        const float fi0 = q0 * i00 + q1 * i10 + q2 * i20;
        const float fi1 = q0 * i01 + q1 * i11 + q2 * i21;
        const float fi2 = q0 * i02 + q1 * i12 + q2 * i22;
        const bool  ent_i = ent[base + i] != 0;

        float vx[4], vy[4], vz[4], sd[4], mk[4];

        #pragma unroll
        for (int k = 0; k < 4; ++k) {
            const int j = j0 + k;
            float d0 = fjx[k] - fi0;
            float d1 = fjy[k] - fi1;
            float d2 = fjz[k] - fi2;
            d0 -= rintf(d0) * pb0;   // round-half-even, matches jnp.round
            d1 -= rintf(d1) * pb1;
            d2 -= rintf(d2) * pb2;

            float v0 = d0 * c00 + d1 * c10 + d2 * c20;
            float v1 = d0 * c01 + d1 * c11 + d2 * c21;
            float v2 = d0 * c02 + d1 * c12 + d2 * c22;
            float s  = v0 * v0 + v1 * v1 + v2 * v2;

            // one select -> mask float; value-masking via FMUL (FMA pipe)
            const bool ok = ent_i && ej[k] && (i != j) && (s < RC2);
            const float m = ok ? 1.0f : 0.0f;   // exact 1.0/0.0
            vx[k] = v0 * m;
            vy[k] = v1 * m;
            vz[k] = v2 * m;
            sd[k] = s  * m;
            mk[k] = m;
        }

        // stage into warp-private SMEM slice (STS.128)
        float4* vdst = reinterpret_cast<float4*>(buf + lane * 12);
        vdst[0] = make_float4(vx[0], vy[0], vz[0], vx[1]);
        vdst[1] = make_float4(vy[1], vz[1], vx[2], vy[2]);
        vdst[2] = make_float4(vz[2], vx[3], vy[3], vz[3]);
        *reinterpret_cast<float4*>(buf + W_SOD + lane * 4) =
            make_float4(sd[0], sd[1], sd[2], sd[3]);
        *reinterpret_cast<float4*>(buf + W_MSK + lane * 4) =
            make_float4(mk[0], mk[1], mk[2], mk[3]);

        __syncwarp();

        if (lane == 0) {
            asm volatile("fence.proxy.async.shared::cta;" ::: "memory");
            const size_t pair = ((size_t)base + i) * N + jwb;
            bulk_store_ef(out + pair * 3,        smem_u32(buf),         WJ * 3 * 4, policy);
            bulk_store_ef(out + sod_off + pair,  smem_u32(buf + W_SOD), WJ * 4,     policy);
            bulk_store_ef(out + mask_off + pair, smem_u32(buf + W_MSK), WJ * 4,     policy);
            asm volatile("cp.async.bulk.commit_group;" ::: "memory");
        }
        __syncwarp();
    }

    // SMEM must stay alive until this warp's TMA reads complete
    if (lane == 0)
        asm volatile("cp.async.bulk.wait_group.read 0;" ::: "memory");
    __syncwarp();
}

extern "C" void kernel_launch(void* const* d_in, const int* in_sizes, int n_in,
                              void* d_out, int out_size)
{
    const float* pos = (const float*)d_in[0];
    const float* cel = (const float*)d_in[1];
    const int*   pbc = (const int*)  d_in[2];
    const int*   ent = (const int*)  d_in[3];
    float* out = (float*)d_out;

    const int B = in_sizes[1] / 9;          // cel_mat has B*9 elements
    const int N = in_sizes[3] / B;          // ent has B*N elements

    dim3 threads(128, 1, 1);
    dim3 blocks(N / JBLK, N / I_TILE, B);
    pair_kernel<<<blocks, threads>>>(pos, cel, pbc, ent, out, N, B);
}

// round 17
// speedup vs baseline: 1.0093x; 1.0089x over previous
#include <cuda_runtime.h>
#include <cstdint>

// ---------------------------------------------------------------------------
// Coo2Cel: periodic minimum-image pair displacements within cutoff.
// Inputs: pos_xyz [B,N,3] f32, cel_mat [B,3,3] f32, pbc [B,3] i32, ent [B,N] i32
// Output (single f32 buffer): vec [B,N,N,3] ++ sod [B,N,N] ++ mask [B,N,N]
//
// Champion structure (R14) + R17: the three bulk-async stores per iteration
// are issued by three different lanes (0:vec, 1:sod, 2:mask), each owning its
// own bulk_group commit/wait — parallelizing TMA issue cost and drain waits
// that were previously serialized on lane 0.
//  - single fused kernel; frac coords recomputed per block prologue
//  - compute -> STS.128 into warp-private double buffers
//  - drained via cp.async.bulk with L2::evict_first (write-once output)
//  - zero block-wide barriers: per-warp pipelines, __syncwarp only
// ---------------------------------------------------------------------------

#define RC2 36.0f   // rc = 6.0
#define I_TILE 4
#define JBLK 512          // j's per block (128 threads x 4)
#define WJ 128            // j's per warp
#define WARP_FLOATS (WJ * 5)   // 640: vec 384 | sod 128 | mask 128
#define W_SOD (WJ * 3)         // 384
#define W_MSK (WJ * 4)         // 512

__device__ __forceinline__ uint32_t smem_u32(const void* p) {
    uint32_t a;
    asm("{ .reg .u64 t; cvta.to.shared.u64 t, %1; cvt.u32.u64 %0, t; }"
        : "=r"(a) : "l"(p));
    return a;
}

__device__ __forceinline__ void bulk_store_ef(const float* gdst, uint32_t ssrc,
                                              int nbytes, uint64_t policy) {
    asm volatile(
        "cp.async.bulk.global.shared::cta.bulk_group.L2::cache_hint "
        "[%0], [%1], %2, %3;"
        :: "l"(gdst), "r"(ssrc), "r"(nbytes), "l"(policy) : "memory");
}

__global__ void __launch_bounds__(128)
pair_kernel(const float* __restrict__ pos,
            const float* __restrict__ cel,
            const int*   __restrict__ pbc,
            const int*   __restrict__ ent,
            float* __restrict__ out,
            int N, int B)
{
    // [buffer][warp][floats] — each warp's slice is contiguous & 16B aligned
    __shared__ __align__(16) float sbuf[2][4][WARP_FLOATS];

    const int b    = blockIdx.z;
    const int i0   = blockIdx.y * I_TILE;
    const int jb   = blockIdx.x * JBLK;
    const int warp = threadIdx.x >> 5;
    const int lane = threadIdx.x & 31;
    const int jwb  = jb + warp * WJ;      // warp's j base
    const int j0   = jwb + lane * 4;

    // --- cell matrix + inverse (prologue; registers die after use) ---------
    const float* c = cel + b * 9;
    const float c00 = c[0], c01 = c[1], c02 = c[2];
    const float c10 = c[3], c11 = c[4], c12 = c[5];
    const float c20 = c[6], c21 = c[7], c22 = c[8];

    const float det = c00 * (c11 * c22 - c12 * c21)
                    - c01 * (c10 * c22 - c12 * c20)
                    + c02 * (c10 * c21 - c11 * c20);
    const float r = 1.0f / det;
    const float i00 = (c11 * c22 - c12 * c21) * r;
    const float i01 = (c02 * c21 - c01 * c22) * r;
    const float i02 = (c01 * c12 - c02 * c11) * r;
    const float i10 = (c12 * c20 - c10 * c22) * r;
    const float i11 = (c00 * c22 - c02 * c20) * r;
    const float i12 = (c02 * c10 - c00 * c12) * r;
    const float i20 = (c10 * c21 - c11 * c20) * r;
    const float i21 = (c01 * c20 - c00 * c21) * r;
    const float i22 = (c00 * c11 - c01 * c10) * r;

    const float pb0 = pbc[b * 3 + 0] ? 1.0f : 0.0f;
    const float pb1 = pbc[b * 3 + 1] ? 1.0f : 0.0f;
    const float pb2 = pbc[b * 3 + 2] ? 1.0f : 0.0f;

    // evict_first policy for write-once output
    uint64_t policy;
    asm("createpolicy.fractional.L2::evict_first.b64 %0, 1.0;" : "=l"(policy));

    const int base = b * N;

    // --- j-side fracs: computed ONCE from pos, reused for all I_TILE i's ---
    const float4* pj4 = reinterpret_cast<const float4*>(pos + ((size_t)base + j0) * 3);
    const float4 pa = pj4[0];
    const float4 pb4 = pj4[1];
    const float4 pc = pj4[2];
    const float pj[12] = { pa.x, pa.y, pa.z, pa.w,
                           pb4.x, pb4.y, pb4.z, pb4.w,
                           pc.x, pc.y, pc.z, pc.w };

    float fjx[4], fjy[4], fjz[4];
    #pragma unroll
    for (int k = 0; k < 4; ++k) {
        const float p0 = pj[k * 3 + 0];
        const float p1 = pj[k * 3 + 1];
        const float p2 = pj[k * 3 + 2];
        fjx[k] = p0 * i00 + p1 * i10 + p2 * i20;
        fjy[k] = p0 * i01 + p1 * i11 + p2 * i21;
        fjz[k] = p0 * i02 + p1 * i12 + p2 * i22;
    }

    const int4 ej4 = *reinterpret_cast<const int4*>(ent + base + j0);
    const bool ej[4] = { ej4.x != 0, ej4.y != 0, ej4.z != 0, ej4.w != 0 };

    const size_t NN       = (size_t)N * N;
    const size_t sod_off  = (size_t)B * NN * 3;
    const size_t mask_off = (size_t)B * NN * 4;

    #pragma unroll 1
    for (int t = 0; t < I_TILE; ++t) {
        const int i = i0 + t;
        float* buf = sbuf[t & 1][warp];

        // per-lane backpressure: each issuing lane (0..2) owns one group per
        // iteration; its group for this buffer was committed at t-2.
        if (t >= 2) {
            if (lane < 3)
                asm volatile("cp.async.bulk.wait_group.read 1;" ::: "memory");
            __syncwarp();
        }

        // i-side frac: broadcast loads + one mat-vec (cheap)
        const float q0 = pos[((size_t)base + i) * 3 + 0];
        const float q1 = pos[((size_t)base + i) * 3 + 1];
        const float q2 = pos[((size_t)base + i) * 3 + 2];
        const float fi0 = q0 * i00 + q1 * i10 + q2 * i20;
        const float fi1 = q0 * i01 + q1 * i11 + q2 * i21;
        const float fi2 = q0 * i02 + q1 * i12 + q2 * i22;
        const bool  ent_i = ent[base + i] != 0;

        float vx[4], vy[4], vz[4], sd[4], mk[4];

        #pragma unroll
        for (int k = 0; k < 4; ++k) {
            const int j = j0 + k;
            float d0 = fjx[k] - fi0;
            float d1 = fjy[k] - fi1;
            float d2 = fjz[k] - fi2;
            d0 -= rintf(d0) * pb0;   // round-half-even, matches jnp.round
            d1 -= rintf(d1) * pb1;
            d2 -= rintf(d2) * pb2;

            float v0 = d0 * c00 + d1 * c10 + d2 * c20;
            float v1 = d0 * c01 + d1 * c11 + d2 * c21;
            float v2 = d0 * c02 + d1 * c12 + d2 * c22;
            float s  = v0 * v0 + v1 * v1 + v2 * v2;

            // one select -> mask float; value-masking via FMUL (FMA pipe)
            const bool ok = ent_i && ej[k] && (i != j) && (s < RC2);
            const float m = ok ? 1.0f : 0.0f;   // exact 1.0/0.0
            vx[k] = v0 * m;
            vy[k] = v1 * m;
            vz[k] = v2 * m;
            sd[k] = s  * m;
            mk[k] = m;
        }

        // stage into warp-private SMEM slice (STS.128)
        float4* vdst = reinterpret_cast<float4*>(buf + lane * 12);
        vdst[0] = make_float4(vx[0], vy[0], vz[0], vx[1]);
        vdst[1] = make_float4(vy[1], vz[1], vx[2], vy[2]);
        vdst[2] = make_float4(vz[2], vx[3], vy[3], vz[3]);
        *reinterpret_cast<float4*>(buf + W_SOD + lane * 4) =
            make_float4(sd[0], sd[1], sd[2], sd[3]);
        *reinterpret_cast<float4*>(buf + W_MSK + lane * 4) =
            make_float4(mk[0], mk[1], mk[2], mk[3]);

        __syncwarp();

        // three lanes issue the three streams in parallel, each its own group
        if (lane < 3) {
            asm volatile("fence.proxy.async.shared::cta;" ::: "memory");
            const size_t pair = ((size_t)base + i) * N + jwb;
            if (lane == 0) {
                bulk_store_ef(out + pair * 3, smem_u32(buf), WJ * 3 * 4, policy);
            } else if (lane == 1) {
                bulk_store_ef(out + sod_off + pair, smem_u32(buf + W_SOD), WJ * 4, policy);
            } else {
                bulk_store_ef(out + mask_off + pair, smem_u32(buf + W_MSK), WJ * 4, policy);
            }
            asm volatile("cp.async.bulk.commit_group;" ::: "memory");
        }
        __syncwarp();
    }

    // SMEM must stay alive until all this warp's TMA reads complete
    if (lane < 3)
        asm volatile("cp.async.bulk.wait_group.read 0;" ::: "memory");
    __syncwarp();
}

extern "C" void kernel_launch(void* const* d_in, const int* in_sizes, int n_in,
                              void* d_out, int out_size)
{
    const float* pos = (const float*)d_in[0];
    const float* cel = (const float*)d_in[1];
    const int*   pbc = (const int*)  d_in[2];
    const int*   ent = (const int*)  d_in[3];
    float* out = (float*)d_out;

    const int B = in_sizes[1] / 9;          // cel_mat has B*9 elements
    const int N = in_sizes[3] / B;          // ent has B*N elements

    dim3 threads(128, 1, 1);
    dim3 blocks(N / JBLK, N / I_TILE, B);
    pair_kernel<<<blocks, threads>>>(pos, cel, pbc, ent, out, N, B);
}